// round 6
// baseline (speedup 1.0000x reference)
#include <cuda_runtime.h>
#include <cstdint>

// Harmonic lattice potential — R5
//   inputs: pos (N,3) f32, edge_index (2,E) int32, batch (N,) int32 (sorted)
//   output: energy (64,) f32 ++ forces (N,3) f32
//
// R5 changes vs R4 (regressed 64.0) / R3 (60.1):
//   - PDL reverted (it serialized prep behind waiting edge CTAs).
//   - prep no longer zeroes g_acc: finalize restores g_acc[n]=0 after
//     reading it (module-load zero-init establishes the invariant; every
//     call re-establishes it -> deterministic on every call).
//   - prep vectorized: pos read as float4 (3 LDG.128 -> 4 nodes), fully
//     coalesced, ~3x fewer load wavefronts.
//   - edge kernel unchanged: at its random-wavefront floor (~4 wf/edge).

#define NUM_GRAPHS 64
#define MAXN 131072

__device__ float4 g_acc[MAXN];    // force.xyz + energy.w accumulator (zero at entry)
__device__ float4 g_pos4[MAXN];   // packed positions

__device__ __forceinline__ void red_add_v4(float4* addr, float a, float b, float c, float d) {
    asm volatile("red.global.add.v4.f32 [%0], {%1, %2, %3, %4};"
                 :: "l"(addr), "f"(a), "f"(b), "f"(c), "f"(d));
}

// Vector prep: N % 4 == 0 path. G = N/4 groups; thread t packs nodes 4t..4t+3.
__global__ void prep_vec_kernel(const float4* __restrict__ posv,
                                float* __restrict__ out, int G) {
    int t = blockIdx.x * blockDim.x + threadIdx.x;
    if (t < G) {
        float4 a = __ldg(&posv[3 * t + 0]);   // x0 y0 z0 x1
        float4 b = __ldg(&posv[3 * t + 1]);   // y1 z1 x2 y2
        float4 c = __ldg(&posv[3 * t + 2]);   // z2 x3 y3 z3
        g_pos4[4 * t + 0] = make_float4(a.x, a.y, a.z, 0.f);
        g_pos4[4 * t + 1] = make_float4(a.w, b.x, b.y, 0.f);
        g_pos4[4 * t + 2] = make_float4(b.z, b.w, c.x, 0.f);
        g_pos4[4 * t + 3] = make_float4(c.y, c.z, c.w, 0.f);
    }
    if (t < NUM_GRAPHS) out[t] = 0.f;   // zero energy slots (d_out poisoned)
}

// Scalar prep fallback (N % 4 != 0).
__global__ void prep_scalar_kernel(const float* __restrict__ pos,
                                   float* __restrict__ out, int N) {
    int t = blockIdx.x * blockDim.x + threadIdx.x;
    if (t < N)
        g_pos4[t] = make_float4(__ldg(&pos[3 * t]), __ldg(&pos[3 * t + 1]),
                                __ldg(&pos[3 * t + 2]), 0.f);
    if (t < NUM_GRAPHS) out[t] = 0.f;
}

// Vector path: E % 4 == 0. One quad (4 edges) per thread, exact grid.
__global__ void __launch_bounds__(256)
edge_vec_kernel(const int4* __restrict__ ia, const int4* __restrict__ ja, int Q) {
    int q = blockIdx.x * blockDim.x + threadIdx.x;
    if (q >= Q) return;

    int4 iv = __ldg(&ia[q]);
    int4 jv = __ldg(&ja[q]);
    int is[4] = {iv.x, iv.y, iv.z, iv.w};
    int js[4] = {jv.x, jv.y, jv.z, jv.w};

    float4 pi[4], pj[4];
#pragma unroll
    for (int k = 0; k < 4; k++) {
        pi[k] = __ldg(&g_pos4[is[k]]);
        pj[k] = __ldg(&g_pos4[js[k]]);
    }

#pragma unroll
    for (int k = 0; k < 4; k++) {
        float dx = pi[k].x - pj[k].x;
        float dy = pi[k].y - pj[k].y;
        float dz = pi[k].z - pj[k].z;
        float dd = fmaf(dx, dx, fmaf(dy, dy, dz * dz));
        float rinv = rsqrtf(fmaxf(dd, 1e-40f));
        float d = dd * rinv;                  // = sqrt(dd); 0 when dd==0
        float delta = d - 1.0f;               // K = 1, R0 = 1
        float e = 0.5f * delta * delta;
        float s = delta * rinv;               // dx==0 when dd==0 -> force 0
        float fx = s * dx, fy = s * dy, fz = s * dz;

        red_add_v4(&g_acc[is[k]], -fx, -fy, -fz, e);
        red_add_v4(&g_acc[js[k]],  fx,  fy,  fz, 0.f);
    }
}

// Scalar fallback (E % 4 != 0 — not expected for this dataset).
__global__ void edge_scalar_kernel(const int* __restrict__ ei, int E) {
    int e = blockIdx.x * blockDim.x + threadIdx.x;
    if (e >= E) return;
    int i = __ldg(&ei[e]);
    int j = __ldg(&ei[E + e]);
    float4 pi = __ldg(&g_pos4[i]);
    float4 pj = __ldg(&g_pos4[j]);
    float dx = pi.x - pj.x, dy = pi.y - pj.y, dz = pi.z - pj.z;
    float dd = fmaf(dx, dx, fmaf(dy, dy, dz * dz));
    float rinv = rsqrtf(fmaxf(dd, 1e-40f));
    float d = dd * rinv;
    float delta = d - 1.0f;
    float e2 = 0.5f * delta * delta;
    float s = delta * rinv;
    float fx = s * dx, fy = s * dy, fz = s * dz;
    red_add_v4(&g_acc[i], -fx, -fy, -fz, e2);
    red_add_v4(&g_acc[j],  fx,  fy,  fz, 0.f);
}

__global__ void finalize_kernel(float* __restrict__ out,
                                const int* __restrict__ batch, int N) {
    __shared__ float ebins[NUM_GRAPHS];
    int t = threadIdx.x;
    if (t < NUM_GRAPHS) ebins[t] = 0.f;
    __syncthreads();

    int n = blockIdx.x * blockDim.x + t;
    if (n < N) {
        float4 a = g_acc[n];
        out[NUM_GRAPHS + 3 * n + 0] = a.x;
        out[NUM_GRAPHS + 3 * n + 1] = a.y;
        out[NUM_GRAPHS + 3 * n + 2] = a.z;
        g_acc[n] = make_float4(0.f, 0.f, 0.f, 0.f);  // restore entry invariant
        atomicAdd(&ebins[__ldg(&batch[n])], a.w);    // sorted batch: ~1 bin per block
    }
    __syncthreads();
    if (t < NUM_GRAPHS) {
        float v = ebins[t];
        if (v != 0.f) atomicAdd(&out[t], v);
    }
}

extern "C" void kernel_launch(void* const* d_in, const int* in_sizes, int n_in,
                              void* d_out, int out_size) {
    const float* pos   = (const float*)d_in[0];
    const int*   ei    = (const int*)d_in[1];
    const int*   batch = (const int*)d_in[2];
    float* out = (float*)d_out;

    int N = in_sizes[0] / 3;
    int E = in_sizes[1] / 2;

    if ((N & 3) == 0) {
        int G = N >> 2;
        int threads = 128;
        int blocks  = (G + threads - 1) / threads;
        prep_vec_kernel<<<blocks, threads>>>((const float4*)pos, out, G);
    } else {
        int threads = 128;
        int blocks  = (N + threads - 1) / threads;
        prep_scalar_kernel<<<blocks, threads>>>(pos, out, N);
    }
    if ((E & 3) == 0) {
        int Q = E >> 2;
        int threads = 256;
        int blocks  = (Q + threads - 1) / threads;
        edge_vec_kernel<<<blocks, threads>>>((const int4*)ei, (const int4*)(ei + E), Q);
    } else {
        int threads = 256;
        int blocks  = (E + threads - 1) / threads;
        edge_scalar_kernel<<<blocks, threads>>>(ei, E);
    }
    {
        int threads = 256;
        int blocks  = (N + threads - 1) / threads;
        finalize_kernel<<<blocks, threads>>>(out, batch, N);
    }
}

// round 7
// speedup vs baseline: 1.0360x; 1.0360x over previous
#include <cuda_runtime.h>
#include <cstdint>

// Harmonic lattice potential — R6 (R3 base + 8 edges/thread in edge kernel)
//   inputs: pos (N,3) f32, edge_index (2,E) int32, batch (N,) int32 (sorted)
//   output: energy (64,) f32 ++ forces (N,3) f32
//
// R6 vs R3 (60.1us): edge kernel processes 8 edges/thread (2x int4 loads per
// endpoint list, all 16 pos gathers front-batched) for higher MLP and fewer
// wave transitions. prep/finalize identical to R3 (launch-ramp bound; R5
// showed touching them regresses).

#define R0 1.0f
#define NUM_GRAPHS 64
#define MAXN 131072

__device__ float4 g_acc[MAXN];    // force.xyz + energy.w accumulator
__device__ float4 g_pos4[MAXN];   // packed positions

__device__ __forceinline__ void red_add_v4(float4* addr, float a, float b, float c, float d) {
    asm volatile("red.global.add.v4.f32 [%0], {%1, %2, %3, %4};"
                 :: "l"(addr), "f"(a), "f"(b), "f"(c), "f"(d));
}

__global__ void prep_kernel(const float* __restrict__ pos, float* __restrict__ out, int N) {
    int t = blockIdx.x * blockDim.x + threadIdx.x;
    if (t < N) {
        g_acc[t]  = make_float4(0.f, 0.f, 0.f, 0.f);
        g_pos4[t] = make_float4(__ldg(&pos[3 * t]), __ldg(&pos[3 * t + 1]),
                                __ldg(&pos[3 * t + 2]), 0.f);
    }
    if (t < NUM_GRAPHS) out[t] = 0.f;   // zero energy slots (d_out poisoned)
}

// Octet path: E % 8 == 0 (E = 3.2M). O = E/8 octets, one per thread.
__global__ void __launch_bounds__(256)
edge_oct_kernel(const int4* __restrict__ ia, const int4* __restrict__ ja, int O) {
    int o = blockIdx.x * blockDim.x + threadIdx.x;
    if (o >= O) return;

    int4 iv0 = __ldg(&ia[2 * o]);
    int4 iv1 = __ldg(&ia[2 * o + 1]);
    int4 jv0 = __ldg(&ja[2 * o]);
    int4 jv1 = __ldg(&ja[2 * o + 1]);
    int is[8] = {iv0.x, iv0.y, iv0.z, iv0.w, iv1.x, iv1.y, iv1.z, iv1.w};
    int js[8] = {jv0.x, jv0.y, jv0.z, jv0.w, jv1.x, jv1.y, jv1.z, jv1.w};

    float4 pi[8], pj[8];
#pragma unroll
    for (int k = 0; k < 8; k++) {
        pi[k] = __ldg(&g_pos4[is[k]]);
        pj[k] = __ldg(&g_pos4[js[k]]);
    }

#pragma unroll
    for (int k = 0; k < 8; k++) {
        float dx = pi[k].x - pj[k].x;
        float dy = pi[k].y - pj[k].y;
        float dz = pi[k].z - pj[k].z;
        float dd = fmaf(dx, dx, fmaf(dy, dy, dz * dz));
        float rinv = rsqrtf(fmaxf(dd, 1e-40f));
        float d = dd * rinv;                  // = sqrt(dd); 0 when dd==0
        float delta = d - R0;                 // K = 1
        float e = 0.5f * delta * delta;
        float s = delta * rinv;               // dx==0 when dd==0 -> force 0
        float fx = s * dx, fy = s * dy, fz = s * dz;

        red_add_v4(&g_acc[is[k]], -fx, -fy, -fz, e);
        red_add_v4(&g_acc[js[k]],  fx,  fy,  fz, 0.f);
    }
}

// Scalar fallback (E % 8 != 0 — not expected for this dataset).
__global__ void edge_scalar_kernel(const int* __restrict__ ei, int E) {
    int e = blockIdx.x * blockDim.x + threadIdx.x;
    if (e >= E) return;
    int i = __ldg(&ei[e]);
    int j = __ldg(&ei[E + e]);
    float4 pi = __ldg(&g_pos4[i]);
    float4 pj = __ldg(&g_pos4[j]);
    float dx = pi.x - pj.x, dy = pi.y - pj.y, dz = pi.z - pj.z;
    float dd = fmaf(dx, dx, fmaf(dy, dy, dz * dz));
    float rinv = rsqrtf(fmaxf(dd, 1e-40f));
    float d = dd * rinv;
    float delta = d - R0;
    float e2 = 0.5f * delta * delta;
    float s = delta * rinv;
    float fx = s * dx, fy = s * dy, fz = s * dz;
    red_add_v4(&g_acc[i], -fx, -fy, -fz, e2);
    red_add_v4(&g_acc[j],  fx,  fy,  fz, 0.f);
}

__global__ void finalize_kernel(float* __restrict__ out,
                                const int* __restrict__ batch, int N) {
    __shared__ float ebins[NUM_GRAPHS];
    int t = threadIdx.x;
    if (t < NUM_GRAPHS) ebins[t] = 0.f;
    __syncthreads();

    int n = blockIdx.x * blockDim.x + t;
    if (n < N) {
        float4 a = g_acc[n];
        out[NUM_GRAPHS + 3 * n + 0] = a.x;
        out[NUM_GRAPHS + 3 * n + 1] = a.y;
        out[NUM_GRAPHS + 3 * n + 2] = a.z;
        atomicAdd(&ebins[__ldg(&batch[n])], a.w);   // sorted batch: ~1 bin per block
    }
    __syncthreads();
    if (t < NUM_GRAPHS) {
        float v = ebins[t];
        if (v != 0.f) atomicAdd(&out[t], v);
    }
}

extern "C" void kernel_launch(void* const* d_in, const int* in_sizes, int n_in,
                              void* d_out, int out_size) {
    const float* pos   = (const float*)d_in[0];
    const int*   ei    = (const int*)d_in[1];
    const int*   batch = (const int*)d_in[2];
    float* out = (float*)d_out;

    int N = in_sizes[0] / 3;
    int E = in_sizes[1] / 2;

    {
        int threads = 128;
        int blocks  = (N + threads - 1) / threads;
        prep_kernel<<<blocks, threads>>>(pos, out, N);
    }
    if ((E & 7) == 0) {
        int O = E >> 3;
        int threads = 256;
        int blocks  = (O + threads - 1) / threads;
        edge_oct_kernel<<<blocks, threads>>>((const int4*)ei, (const int4*)(ei + E), O);
    } else {
        int threads = 256;
        int blocks  = (E + threads - 1) / threads;
        edge_scalar_kernel<<<blocks, threads>>>(ei, E);
    }
    {
        int threads = 128;
        int blocks  = (N + threads - 1) / threads;
        finalize_kernel<<<blocks, threads>>>(out, batch, N);
    }
}